// round 13
// baseline (speedup 1.0000x reference)
#include <cuda_runtime.h>
#include <cstdint>

// MaskedMSE: B=16, C=4, H=W=512 — cp.async.bulk (TMA-class) pipelined kernel.
// input : d_in[0]  float32 [16, 4, 512, 512]
// target: d_in[1]  float32 [16, 5, 512, 512]  (channel 4 is the {0,1} mask)
// out   : d_out    float32 [1]
//
// 256 streaming blocks (16 per batch), each processes 16 chunks of 1024 px.
// Per chunk, thread 0 issues 9 x 4KB cp.async.bulk copies (mask, 4 input ch,
// 4 target ch) into a 36KB SMEM stage; double-buffered with mbarrier
// expect_tx completion. Long sequential bursts -> better DRAM efficiency
// than 9-way interleaved LDG streams.
// Block 256 is a spinner/folder: waits for a release-ticket to reach 256,
// folds partials in FIXED order (atomics only count -> deterministic),
// per_b = cnt>0 ? sse/(C*cnt) : 0, writes mean over B, resets the ticket.

#define HW        262144
#define CH        4
#define BATCH     16
#define BPB       16                    // streaming blocks per batch
#define TPB       256
#define NSTREAM   (BATCH * BPB)         // 256
#define CHUNK_PX  1024
#define NCHUNK    16                    // 16 * 1024 * 16 blocks = 262144 px ✓
#define STAGE_F4  2304                  // 9 streams * 256 float4
#define STAGE_BYTES 36864u
#define DYN_SMEM  (2 * 36864)           // two stages

__device__ float2       g_partials[NSTREAM];
__device__ unsigned int g_ticket = 0;

__global__ __launch_bounds__(TPB) void masked_mse_bulk(
    const float* __restrict__ input,
    const float* __restrict__ target,
    float* __restrict__ out)
{
    extern __shared__ float4 sdyn[];
    __shared__ __align__(8) unsigned long long s_mbar[2];

    const int tid  = threadIdx.x;
    const int lane = tid & 31;
    const int wid  = tid >> 5;

    // ---------------- folder block ----------------
    if (blockIdx.x == NSTREAM) {
        if (tid == 0) {
            unsigned int v;
            for (;;) {
                asm volatile("ld.acquire.gpu.global.u32 %0, [%1];"
                             : "=r"(v) : "l"(&g_ticket) : "memory");
                if (v >= NSTREAM) break;
                __nanosleep(64);
            }
        }
        __syncthreads();

        __shared__ float s_per_b[BATCH];
        #pragma unroll
        for (int i = 0; i < 2; i++) {
            const int b = wid * 2 + i;
            float bs = 0.0f, bc = 0.0f;
            if (lane < BPB) {
                const float2 p = __ldcg(&g_partials[b * BPB + lane]);
                bs = p.x; bc = p.y;
            }
            #pragma unroll
            for (int o = 8; o > 0; o >>= 1) {
                bs += __shfl_down_sync(0xFFFFFFFFu, bs, o);
                bc += __shfl_down_sync(0xFFFFFFFFu, bc, o);
            }
            if (lane == 0)
                s_per_b[b] = (bc > 0.0f) ? bs / ((float)CH * bc) : 0.0f;
        }
        __syncthreads();

        if (tid == 0) {
            float total = 0.0f;
            #pragma unroll
            for (int i = 0; i < BATCH; i++) total += s_per_b[i];
            out[0] = total / (float)BATCH;
            g_ticket = 0;   // reset for next graph replay
        }
        return;
    }

    // ---------------- streaming blocks ----------------
    const int b   = blockIdx.x >> 4;
    const int sub = blockIdx.x & 15;

    const float* in_base = input  + (size_t)b * CH * HW;
    const float* tg_base = target + (size_t)b * (CH + 1) * HW;
    const float* mk_base = tg_base + (size_t)CH * HW;

    const uint32_t mbar0 = (uint32_t)__cvta_generic_to_shared(&s_mbar[0]);
    const uint32_t mbar1 = (uint32_t)__cvta_generic_to_shared(&s_mbar[1]);
    const uint32_t sbase = (uint32_t)__cvta_generic_to_shared(&sdyn[0]);

    if (tid == 0) {
        asm volatile("mbarrier.init.shared.b64 [%0], 1;" :: "r"(mbar0) : "memory");
        asm volatile("mbarrier.init.shared.b64 [%0], 1;" :: "r"(mbar1) : "memory");
        asm volatile("fence.proxy.async.shared::cta;" ::: "memory");
    }
    __syncthreads();

    // Issue chunk c's 9 bulk copies into stage c&1 (thread 0 only).
    auto issue = [&](int c) {
        const int s = c & 1;
        const uint32_t mba = s ? mbar1 : mbar0;
        const uint32_t dst = sbase + (uint32_t)s * STAGE_BYTES;
        const size_t   px0 = ((size_t)sub * NCHUNK + c) * CHUNK_PX;

        asm volatile("mbarrier.arrive.expect_tx.shared.b64 _, [%0], %1;"
                     :: "r"(mba), "r"(STAGE_BYTES) : "memory");
        // mask (4KB)
        asm volatile(
            "cp.async.bulk.shared::cta.global.mbarrier::complete_tx::bytes [%0], [%1], %2, [%3];"
            :: "r"(dst), "l"(mk_base + px0), "r"(4096u), "r"(mba) : "memory");
        #pragma unroll
        for (int ch = 0; ch < CH; ch++) {
            asm volatile(
                "cp.async.bulk.shared::cta.global.mbarrier::complete_tx::bytes [%0], [%1], %2, [%3];"
                :: "r"(dst + 4096u * (1 + ch)), "l"(in_base + (size_t)ch * HW + px0),
                   "r"(4096u), "r"(mba) : "memory");
            asm volatile(
                "cp.async.bulk.shared::cta.global.mbarrier::complete_tx::bytes [%0], [%1], %2, [%3];"
                :: "r"(dst + 4096u * (5 + ch)), "l"(tg_base + (size_t)ch * HW + px0),
                   "r"(4096u), "r"(mba) : "memory");
        }
    };

    float sse = 0.0f;
    float cnt = 0.0f;

    if (tid == 0) { issue(0); issue(1); }

    for (int c = 0; c < NCHUNK; c++) {
        const int      s   = c & 1;
        const unsigned ph  = (unsigned)(c >> 1) & 1u;
        const uint32_t mba = s ? mbar1 : mbar0;

        // acquire-wait on stage full
        unsigned done;
        do {
            asm volatile(
                "{\n\t.reg .pred p;\n\t"
                "mbarrier.try_wait.parity.acquire.cta.shared::cta.b64 p, [%1], %2, 0x989680;\n\t"
                "selp.b32 %0, 1, 0, p;\n\t}"
                : "=r"(done) : "r"(mba), "r"(ph) : "memory");
        } while (!done);

        const float4* st = &sdyn[s * STAGE_F4];
        const float4  m  = st[tid];
        cnt += m.x + m.y + m.z + m.w;
        #pragma unroll
        for (int ch = 0; ch < CH; ch++) {
            const float4 a = st[256 + (ch << 8) + tid];
            const float4 t = st[1280 + (ch << 8) + tid];
            const float dx = a.x - t.x;
            const float dy = a.y - t.y;
            const float dz = a.z - t.z;
            const float dw = a.w - t.w;
            sse += m.x * (dx * dx); sse += m.y * (dy * dy);
            sse += m.z * (dz * dz); sse += m.w * (dw * dw);
        }

        __syncthreads();                 // all threads done reading stage s
        if (tid == 0 && c + 2 < NCHUNK) issue(c + 2);
    }

    // ---- block reduce + partial + release ticket ----
    #pragma unroll
    for (int o = 16; o > 0; o >>= 1) {
        sse += __shfl_down_sync(0xFFFFFFFFu, sse, o);
        cnt += __shfl_down_sync(0xFFFFFFFFu, cnt, o);
    }

    __shared__ float s_sse[TPB / 32];
    __shared__ float s_cnt[TPB / 32];
    if (lane == 0) { s_sse[wid] = sse; s_cnt[wid] = cnt; }
    __syncthreads();

    if (wid != 0) return;

    sse = (lane < TPB / 32) ? s_sse[lane] : 0.0f;
    cnt = (lane < TPB / 32) ? s_cnt[lane] : 0.0f;
    #pragma unroll
    for (int o = 4; o > 0; o >>= 1) {
        sse += __shfl_down_sync(0xFFFFFFFFu, sse, o);
        cnt += __shfl_down_sync(0xFFFFFFFFu, cnt, o);
    }

    if (lane == 0) {
        g_partials[b * BPB + sub] = make_float2(sse, cnt);
        asm volatile("red.release.gpu.global.add.u32 [%0], 1;"
                     :: "l"(&g_ticket) : "memory");
    }
}

extern "C" void kernel_launch(void* const* d_in, const int* in_sizes, int n_in,
                              void* d_out, int out_size)
{
    const float* input  = (const float*)d_in[0];
    const float* target = (const float*)d_in[1];
    float*       out    = (float*)d_out;

    cudaFuncSetAttribute(masked_mse_bulk,
                         cudaFuncAttributeMaxDynamicSharedMemorySize, DYN_SMEM);
    masked_mse_bulk<<<NSTREAM + 1, TPB, DYN_SMEM>>>(input, target, out);
}

// round 17
// speedup vs baseline: 1.3651x; 1.3651x over previous
#include <cuda_runtime.h>

// MaskedMSE: B=16, C=4, H=W=512 — single kernel; 1024 streaming blocks +
// one dedicated spinner/folder block. Streaming loads use __ldcs
// (evict-first: zero-reuse data stays out of L2 ways).
//
// input : d_in[0]  float32 [16, 4, 512, 512]
// target: d_in[1]  float32 [16, 5, 512, 512]  (channel 4 is the {0,1} mask)
// out   : d_out    float32 [1]
//
// Streaming block i (i < 1024): batch b = i>>6, sub-block blk = i&63.
//   Computes (masked SSE, mask count) partial, stores it, then
//   red.release.gpu.add g_ticket, 1   (release orders the partial store).
// Folder block (i == 1024): spins on ld.acquire.gpu g_ticket until 1024,
//   folds all partials in FIXED order (deterministic — atomics only count),
//   per_b = cnt>0 ? sse/(C*cnt) : 0, writes mean over B, resets the ticket
//   for the next graph replay. Zero-init of the ticket is correct on call 1.

#define HW      262144          // 512*512
#define HW4     65536           // HW / 4 (float4 units)
#define CH      4
#define BATCH   16
#define BPB     64              // streaming blocks per batch
#define TPB     256             // threads per block
#define NSTREAM (BATCH * BPB)   // 1024 streaming blocks

__device__ float2       g_partials[NSTREAM];
__device__ unsigned int g_ticket = 0;

__global__ __launch_bounds__(TPB) void masked_mse_final(
    const float* __restrict__ input,
    const float* __restrict__ target,
    float* __restrict__ out)
{
    const int tid  = threadIdx.x;
    const int lane = tid & 31;
    const int wid  = tid >> 5;

    // ---------------- folder block ----------------
    if (blockIdx.x == NSTREAM) {
        if (tid == 0) {
            unsigned int v;
            for (;;) {
                asm volatile("ld.acquire.gpu.global.u32 %0, [%1];"
                             : "=r"(v) : "l"(&g_ticket) : "memory");
                if (v >= NSTREAM) break;
                __nanosleep(64);
            }
        }
        __syncthreads();   // releases once thread 0 has observed completion

        // 8 warps; warp w folds batches 2w and 2w+1 (fixed order).
        __shared__ float s_per_b[BATCH];
        #pragma unroll
        for (int i = 0; i < 2; i++) {
            const int b = wid * 2 + i;
            const float2 p0 = __ldcg(&g_partials[b * BPB + lane]);
            const float2 p1 = __ldcg(&g_partials[b * BPB + lane + 32]);
            float bs = p0.x + p1.x;
            float bc = p0.y + p1.y;
            #pragma unroll
            for (int o = 16; o > 0; o >>= 1) {
                bs += __shfl_down_sync(0xFFFFFFFFu, bs, o);
                bc += __shfl_down_sync(0xFFFFFFFFu, bc, o);
            }
            if (lane == 0)
                s_per_b[b] = (bc > 0.0f) ? bs / ((float)CH * bc) : 0.0f;
        }
        __syncthreads();

        if (tid == 0) {
            float total = 0.0f;
            #pragma unroll
            for (int i = 0; i < BATCH; i++) total += s_per_b[i];
            out[0] = total / (float)BATCH;
            g_ticket = 0;   // reset for the next graph replay
        }
        return;
    }

    // ---------------- streaming blocks ----------------
    const int b   = blockIdx.x >> 6;   // batch
    const int blk = blockIdx.x & 63;   // sub-block within batch

    const float4* __restrict__ inb = (const float4*)(input  + (size_t)b * CH * HW);
    const float4* __restrict__ tgb = (const float4*)(target + (size_t)b * (CH + 1) * HW);
    const float4* __restrict__ mb  = (const float4*)(target + (size_t)b * (CH + 1) * HW + (size_t)CH * HW);

    float sse = 0.0f;
    float cnt = 0.0f;

    // 65536 vec4 per batch / (64 blocks * 256 threads) = 4 iterations/thread
    for (int p = blk * TPB + tid; p < HW4; p += BPB * TPB) {
        const float4 m = __ldcs(&mb[p]);
        cnt += m.x + m.y + m.z + m.w;
        #pragma unroll
        for (int c = 0; c < CH; c++) {
            const float4 a = __ldcs(&inb[c * HW4 + p]);
            const float4 t = __ldcs(&tgb[c * HW4 + p]);
            const float dx = a.x - t.x;
            const float dy = a.y - t.y;
            const float dz = a.z - t.z;
            const float dw = a.w - t.w;
            sse += m.x * (dx * dx);
            sse += m.y * (dy * dy);
            sse += m.z * (dz * dz);
            sse += m.w * (dw * dw);
        }
    }

    // intra-warp reduce
    #pragma unroll
    for (int o = 16; o > 0; o >>= 1) {
        sse += __shfl_down_sync(0xFFFFFFFFu, sse, o);
        cnt += __shfl_down_sync(0xFFFFFFFFu, cnt, o);
    }

    __shared__ float s_sse[TPB / 32];
    __shared__ float s_cnt[TPB / 32];
    if (lane == 0) { s_sse[wid] = sse; s_cnt[wid] = cnt; }
    __syncthreads();

    if (wid != 0) return;

    sse = (lane < TPB / 32) ? s_sse[lane] : 0.0f;
    cnt = (lane < TPB / 32) ? s_cnt[lane] : 0.0f;
    #pragma unroll
    for (int o = 4; o > 0; o >>= 1) {
        sse += __shfl_down_sync(0xFFFFFFFFu, sse, o);
        cnt += __shfl_down_sync(0xFFFFFFFFu, cnt, o);
    }

    if (lane == 0) {
        g_partials[b * BPB + blk] = make_float2(sse, cnt);
        // Release RED: orders the partial store before the count increment.
        asm volatile("red.release.gpu.global.add.u32 [%0], 1;"
                     :: "l"(&g_ticket) : "memory");
    }
}

extern "C" void kernel_launch(void* const* d_in, const int* in_sizes, int n_in,
                              void* d_out, int out_size)
{
    const float* input  = (const float*)d_in[0];
    const float* target = (const float*)d_in[1];
    float*       out    = (float*)d_out;

    masked_mse_final<<<NSTREAM + 1, TPB>>>(input, target, out);
}